// round 3
// baseline (speedup 1.0000x reference)
#include <cuda_runtime.h>
#include <math.h>

#define BB    64
#define DD    256
#define HEADS 8
#define DH    32
#define NTOK  625
#define NPAD  640

// ---- scratch (device globals) ----
__device__ float g_q[BB*HEADS*NTOK*DH];
__device__ float g_k[BB*HEADS*NTOK*DH];
__device__ float g_v[BB*HEADS*NTOK*DH];
__device__ float g_bias[HEADS*NPAD*NPAD];
__device__ float g_o[BB*NTOK*DD];

// ================= TF32 split-mma helpers =================
__device__ __forceinline__ unsigned f2tf(float x) {
    unsigned u; asm("cvt.rna.tf32.f32 %0, %1;" : "=r"(u) : "f"(x)); return u;
}
__device__ __forceinline__ void split(float x, unsigned &h, unsigned &l) {
    h = f2tf(x);
    l = f2tf(x - __uint_as_float(h));
}
// split storing hi/lo as float bit-patterns (for smem staging)
__device__ __forceinline__ void splitf(float x, float &h, float &l) {
    unsigned uh = f2tf(x);
    h = __uint_as_float(uh);
    l = __uint_as_float(f2tf(x - h));
}
__device__ __forceinline__ void mma8(float4 &d, const unsigned a[4],
                                     unsigned b0, unsigned b1) {
    asm volatile(
        "mma.sync.aligned.m16n8k8.row.col.f32.tf32.tf32.f32 "
        "{%0,%1,%2,%3}, {%4,%5,%6,%7}, {%8,%9}, {%0,%1,%2,%3};"
        : "+f"(d.x), "+f"(d.y), "+f"(d.z), "+f"(d.w)
        : "r"(a[0]), "r"(a[1]), "r"(a[2]), "r"(a[3]), "r"(b0), "r"(b1));
}
__device__ __forceinline__ void mma3(float4 &d, const unsigned ah[4],
                                     const unsigned al[4],
                                     unsigned bh0, unsigned bh1,
                                     unsigned bl0, unsigned bl1) {
    mma8(d, ah, bh0, bh1);
    mma8(d, ah, bl0, bl1);
    mma8(d, al, bh0, bh1);
}

// ============================================================
// Kernel 0: bias_fill (j-stride padded to 640)
// ============================================================
__global__ void bias_fill(const float* __restrict__ table,
                          const int*   __restrict__ rel) {
    int idx = blockIdx.x * blockDim.x + threadIdx.x;
    const int total = HEADS * NTOK * NTOK;
    if (idx >= total) return;
    int h = idx / (NTOK * NTOK);
    int r = idx - h * (NTOK * NTOK);
    int i = r / NTOK;
    int j = r - i * NTOK;
    g_bias[(h * NPAD + i) * NPAD + j] = table[rel[r] * HEADS + h];
}

// ============================================================
// Kernel 1: QKV projection. 128(M)x64(N), K=256. Pre-split smem.
// ============================================================
__global__ __launch_bounds__(256) void qkv_mma(const float* __restrict__ x,
                                               const float* __restrict__ w) {
    __shared__ float Ah[16][136], Al[16][136];   // stride 136 (==8 mod 32)
    __shared__ float Bh[16][72],  Bl[16][72];    // stride 72  (==8 mod 32)

    int b  = blockIdx.z;
    int p0 = blockIdx.x * 128;
    int n0 = blockIdx.y * 64;
    int tid = threadIdx.x;
    int wid = tid >> 5, lane = tid & 31;
    int wm = wid & 3, wn = wid >> 2;
    int r = lane >> 2, c = lane & 3;
    const float* xb = x + (size_t)b * DD * NTOK;

    float4 acc[2][4];
    #pragma unroll
    for (int i = 0; i < 2; i++)
        #pragma unroll
        for (int j = 0; j < 4; j++) acc[i][j] = make_float4(0,0,0,0);

    int am = tid & 127;
    int ak = tid >> 7;
    int bk = tid >> 4;
    int bn4 = (tid & 15) * 4;

    for (int k0 = 0; k0 < DD; k0 += 16) {
        #pragma unroll
        for (int i = 0; i < 8; i++) {
            int kk = ak + i * 2;
            float v = (p0 + am < NTOK) ? xb[(size_t)(k0 + kk) * NTOK + p0 + am] : 0.f;
            splitf(v, Ah[kk][am], Al[kk][am]);
        }
        {
            float4 v = *(const float4*)&w[(size_t)(k0 + bk) * (3*DD) + n0 + bn4];
            float4 h4, l4;
            splitf(v.x, h4.x, l4.x); splitf(v.y, h4.y, l4.y);
            splitf(v.z, h4.z, l4.z); splitf(v.w, h4.w, l4.w);
            *(float4*)&Bh[bk][bn4] = h4;
            *(float4*)&Bl[bk][bn4] = l4;
        }
        __syncthreads();

        #pragma unroll
        for (int ktl = 0; ktl < 2; ktl++) {
            unsigned ah[2][4], al[2][4];
            #pragma unroll
            for (int mt = 0; mt < 2; mt++) {
                int mb = wm * 32 + mt * 16;
                ah[mt][0] = __float_as_uint(Ah[ktl*8 + c    ][mb + r    ]);
                ah[mt][1] = __float_as_uint(Ah[ktl*8 + c    ][mb + r + 8]);
                ah[mt][2] = __float_as_uint(Ah[ktl*8 + c + 4][mb + r    ]);
                ah[mt][3] = __float_as_uint(Ah[ktl*8 + c + 4][mb + r + 8]);
                al[mt][0] = __float_as_uint(Al[ktl*8 + c    ][mb + r    ]);
                al[mt][1] = __float_as_uint(Al[ktl*8 + c    ][mb + r + 8]);
                al[mt][2] = __float_as_uint(Al[ktl*8 + c + 4][mb + r    ]);
                al[mt][3] = __float_as_uint(Al[ktl*8 + c + 4][mb + r + 8]);
            }
            #pragma unroll
            for (int nt = 0; nt < 4; nt++) {
                int nb = wn * 32 + nt * 8 + r;
                unsigned bh0 = __float_as_uint(Bh[ktl*8 + c    ][nb]);
                unsigned bh1 = __float_as_uint(Bh[ktl*8 + c + 4][nb]);
                unsigned bl0 = __float_as_uint(Bl[ktl*8 + c    ][nb]);
                unsigned bl1 = __float_as_uint(Bl[ktl*8 + c + 4][nb]);
                #pragma unroll
                for (int mt = 0; mt < 2; mt++)
                    mma3(acc[mt][nt], ah[mt], al[mt], bh0, bh1, bl0, bl1);
            }
        }
        __syncthreads();
    }

    // epilogue: scatter to g_q/g_k/g_v (bh, p, e); q pre-scaled
    #pragma unroll
    for (int nt = 0; nt < 4; nt++) {
        int ng0 = n0 + wn * 32 + nt * 8 + 2 * c;
        int which = ng0 >> 8;
        int h = (ng0 >> 5) & 7;
        int e = ng0 & 31;
        float* dst = (which == 0) ? g_q : (which == 1) ? g_k : g_v;
        float s = (which == 0) ? 0.17677669529663687f : 1.f;
        size_t base = (size_t)(b * HEADS + h) * NTOK * DH + e;
        #pragma unroll
        for (int mt = 0; mt < 2; mt++) {
            int p = p0 + wm * 32 + mt * 16 + r;
            if (p < NTOK)
                *(float2*)&dst[base + (size_t)p * DH] =
                    make_float2(acc[mt][nt].x * s, acc[mt][nt].y * s);
            if (p + 8 < NTOK)
                *(float2*)&dst[base + (size_t)(p + 8) * DH] =
                    make_float2(acc[mt][nt].z * s, acc[mt][nt].w * s);
        }
    }
}

// ============================================================
// Kernel 2: flash attention, pre-split K/V smem, P transposed via
// intra-quad shuffles (no P smem buffer).
// ============================================================
__global__ __launch_bounds__(256) void attn_mma() {
    __shared__ float Ksh[64][36], Ksl[64][36];   // [j][e]
    __shared__ float Vsh[64][40], Vsl[64][40];   // [j][e], stride 40 conflict-free

    int tid = threadIdx.x;
    int wid = tid >> 5, lane = tid & 31;
    int r = lane >> 2, c = lane & 3;

    int q0 = blockIdx.x * 128;
    int bh = blockIdx.y;
    int h = bh & 7;
    const float* qb = g_q + (size_t)bh * NTOK * DH;
    const float* kb = g_k + (size_t)bh * NTOK * DH;
    const float* vb = g_v + (size_t)bh * NTOK * DH;

    // Q fragments resident in registers, pre-split
    unsigned qh[4][4], ql[4][4];
    int pr = q0 + wid * 16 + r;
    #pragma unroll
    for (int kt = 0; kt < 4; kt++) {
        float q00 = (pr     < NTOK) ? qb[(size_t)pr * DH + kt*8 + c      ] : 0.f;
        float q10 = (pr + 8 < NTOK) ? qb[(size_t)(pr+8) * DH + kt*8 + c  ] : 0.f;
        float q01 = (pr     < NTOK) ? qb[(size_t)pr * DH + kt*8 + c + 4  ] : 0.f;
        float q11 = (pr + 8 < NTOK) ? qb[(size_t)(pr+8) * DH + kt*8 + c+4] : 0.f;
        split(q00, qh[kt][0], ql[kt][0]);
        split(q10, qh[kt][1], ql[kt][1]);
        split(q01, qh[kt][2], ql[kt][2]);
        split(q11, qh[kt][3], ql[kt][3]);
    }

    float4 O[4];
    #pragma unroll
    for (int i = 0; i < 4; i++) O[i] = make_float4(0,0,0,0);
    float m0 = -INFINITY, m1 = -INFINITY, l0 = 0.f, l1 = 0.f;

    for (int jt = 0; jt < 10; jt++) {
        int j0 = jt * 64;
        // stage K, V tiles, split once
        {
            int row = tid >> 2, e0 = (tid & 3) * 8;
            int jp = j0 + row;
            float kv[8], vv[8];
            if (jp < NTOK) {
                *(float4*)&kv[0] = *(const float4*)&kb[(size_t)jp * DH + e0];
                *(float4*)&kv[4] = *(const float4*)&kb[(size_t)jp * DH + e0 + 4];
                *(float4*)&vv[0] = *(const float4*)&vb[(size_t)jp * DH + e0];
                *(float4*)&vv[4] = *(const float4*)&vb[(size_t)jp * DH + e0 + 4];
            } else {
                #pragma unroll
                for (int i = 0; i < 8; i++) { kv[i] = 0.f; vv[i] = 0.f; }
            }
            #pragma unroll
            for (int i = 0; i < 8; i++) {
                splitf(kv[i], Ksh[row][e0 + i], Ksl[row][e0 + i]);
                splitf(vv[i], Vsh[row][e0 + i], Vsl[row][e0 + i]);
            }
        }
        __syncthreads();

        // S = Q K^T
        float4 acc[8];
        #pragma unroll
        for (int i = 0; i < 8; i++) acc[i] = make_float4(0,0,0,0);
        #pragma unroll
        for (int kt = 0; kt < 4; kt++) {
            #pragma unroll
            for (int nt = 0; nt < 8; nt++) {
                unsigned bh0 = __float_as_uint(Ksh[nt*8 + r][kt*8 + c    ]);
                unsigned bh1 = __float_as_uint(Ksh[nt*8 + r][kt*8 + c + 4]);
                unsigned bl0 = __float_as_uint(Ksl[nt*8 + r][kt*8 + c    ]);
                unsigned bl1 = __float_as_uint(Ksl[nt*8 + r][kt*8 + c + 4]);
                mma3(acc[nt], qh[kt], ql[kt], bh0, bh1, bl0, bl1);
            }
        }

        // bias + tail mask
        {
            const float* bp = g_bias + ((size_t)(h * NPAD + q0 + wid*16 + r)) * NPAD + j0;
            #pragma unroll
            for (int nt = 0; nt < 8; nt++) {
                float2 b0v = *(const float2*)&bp[nt*8 + 2*c];
                float2 b1v = *(const float2*)&bp[8*NPAD + nt*8 + 2*c];
                acc[nt].x += b0v.x; acc[nt].y += b0v.y;
                acc[nt].z += b1v.x; acc[nt].w += b1v.y;
            }
            if (j0 + 64 > NTOK) {
                #pragma unroll
                for (int nt = 0; nt < 8; nt++) {
                    int jc = j0 + nt*8 + 2*c;
                    if (jc     >= NTOK) { acc[nt].x = -1e30f; acc[nt].z = -1e30f; }
                    if (jc + 1 >= NTOK) { acc[nt].y = -1e30f; acc[nt].w = -1e30f; }
                }
            }
        }

        // online softmax (quad reduce)
        float t0 = -INFINITY, t1 = -INFINITY;
        #pragma unroll
        for (int nt = 0; nt < 8; nt++) {
            t0 = fmaxf(t0, fmaxf(acc[nt].x, acc[nt].y));
            t1 = fmaxf(t1, fmaxf(acc[nt].z, acc[nt].w));
        }
        #pragma unroll
        for (int off = 1; off <= 2; off <<= 1) {
            t0 = fmaxf(t0, __shfl_xor_sync(0xffffffffu, t0, off));
            t1 = fmaxf(t1, __shfl_xor_sync(0xffffffffu, t1, off));
        }
        float mn0 = fmaxf(m0, t0), mn1 = fmaxf(m1, t1);
        float cor0 = __expf(m0 - mn0), cor1 = __expf(m1 - mn1);
        float s0 = 0.f, s1 = 0.f;
        #pragma unroll
        for (int nt = 0; nt < 8; nt++) {
            acc[nt].x = __expf(acc[nt].x - mn0);
            acc[nt].y = __expf(acc[nt].y - mn0);
            acc[nt].z = __expf(acc[nt].z - mn1);
            acc[nt].w = __expf(acc[nt].w - mn1);
            s0 += acc[nt].x + acc[nt].y;
            s1 += acc[nt].z + acc[nt].w;
        }
        #pragma unroll
        for (int off = 1; off <= 2; off <<= 1) {
            s0 += __shfl_xor_sync(0xffffffffu, s0, off);
            s1 += __shfl_xor_sync(0xffffffffu, s1, off);
        }
        l0 = l0 * cor0 + s0;  m0 = mn0;
        l1 = l1 * cor1 + s1;  m1 = mn1;
        #pragma unroll
        for (int i = 0; i < 4; i++) {
            O[i].x *= cor0; O[i].y *= cor0;
            O[i].z *= cor1; O[i].w *= cor1;
        }

        // O += P V : P transposed C->A layout via intra-quad shuffles
        int srcA = (lane & ~3) + (c >> 1);
        int srcB = srcA + 2;
        bool odd = (c & 1);
        #pragma unroll
        for (int kt = 0; kt < 8; kt++) {
            float x0 = __shfl_sync(0xffffffffu, acc[kt].x, srcA);
            float y0 = __shfl_sync(0xffffffffu, acc[kt].y, srcA);
            float z0 = __shfl_sync(0xffffffffu, acc[kt].z, srcA);
            float w0 = __shfl_sync(0xffffffffu, acc[kt].w, srcA);
            float x1 = __shfl_sync(0xffffffffu, acc[kt].x, srcB);
            float y1 = __shfl_sync(0xffffffffu, acc[kt].y, srcB);
            float z1 = __shfl_sync(0xffffffffu, acc[kt].z, srcB);
            float w1 = __shfl_sync(0xffffffffu, acc[kt].w, srcB);
            float a0 = odd ? y0 : x0;   // P[r][kt*8+c]
            float a1 = odd ? w0 : z0;   // P[r+8][kt*8+c]
            float a2 = odd ? y1 : x1;   // P[r][kt*8+c+4]
            float a3 = odd ? w1 : z1;   // P[r+8][kt*8+c+4]
            unsigned ph[4], pl[4];
            split(a0, ph[0], pl[0]);
            split(a1, ph[1], pl[1]);
            split(a2, ph[2], pl[2]);
            split(a3, ph[3], pl[3]);
            #pragma unroll
            for (int nt = 0; nt < 4; nt++) {
                unsigned bh0 = __float_as_uint(Vsh[kt*8 + c    ][nt*8 + r]);
                unsigned bh1 = __float_as_uint(Vsh[kt*8 + c + 4][nt*8 + r]);
                unsigned bl0 = __float_as_uint(Vsl[kt*8 + c    ][nt*8 + r]);
                unsigned bl1 = __float_as_uint(Vsl[kt*8 + c + 4][nt*8 + r]);
                mma3(O[nt], ph, pl, bh0, bh1, bl0, bl1);
            }
        }
        __syncthreads();
    }

    // epilogue
    float inv0 = 1.f / l0, inv1 = 1.f / l1;
    float* ob = g_o + (size_t)(bh >> 3) * NTOK * DD + h * DH;
    #pragma unroll
    for (int nt = 0; nt < 4; nt++) {
        int e = nt*8 + 2*c;
        int p = q0 + wid*16 + r;
        if (p < NTOK)
            *(float2*)&ob[(size_t)p * DD + e] =
                make_float2(O[nt].x * inv0, O[nt].y * inv0);
        if (p + 8 < NTOK)
            *(float2*)&ob[(size_t)(p + 8) * DD + e] =
                make_float2(O[nt].z * inv1, O[nt].w * inv1);
    }
}

// ============================================================
// Kernel 3: output projection + transposed store. Cs unioned
// with the A/B staging buffers (smem 35.3KB).
// ============================================================
#define OUT_AB_FLOATS (2*16*136 + 2*16*72)     // 6656
#define OUT_CS_FLOATS (128*69)                 // 8832
#define OUT_SM_FLOATS (OUT_CS_FLOATS > OUT_AB_FLOATS ? OUT_CS_FLOATS : OUT_AB_FLOATS)

__global__ __launch_bounds__(256) void out_mma(const float* __restrict__ w,
                                               float* __restrict__ out) {
    __shared__ __align__(16) float smbuf[OUT_SM_FLOATS];
    float (*Ah)[136] = (float(*)[136])smbuf;
    float (*Al)[136] = (float(*)[136])(smbuf + 16*136);
    float (*Bh)[72]  = (float(*)[72]) (smbuf + 2*16*136);
    float (*Bl)[72]  = (float(*)[72]) (smbuf + 2*16*136 + 16*72);
    float (*Cs)[69]  = (float(*)[69]) smbuf;

    int b  = blockIdx.z;
    int p0 = blockIdx.x * 128;
    int n0 = blockIdx.y * 64;
    int tid = threadIdx.x;
    int wid = tid >> 5, lane = tid & 31;
    int wm = wid & 3, wn = wid >> 2;
    int r = lane >> 2, c = lane & 3;

    float4 acc[2][4];
    #pragma unroll
    for (int i = 0; i < 2; i++)
        #pragma unroll
        for (int j = 0; j < 4; j++) acc[i][j] = make_float4(0,0,0,0);

    int ap = tid >> 2;
    int ak4 = (tid & 3) * 4;
    int bk = tid >> 4;
    int bn4 = (tid & 15) * 4;

    for (int k0 = 0; k0 < DD; k0 += 16) {
        #pragma unroll
        for (int half = 0; half < 2; half++) {
            int pl = ap + half * 64;
            float4 v = (p0 + pl < NTOK)
                ? *(const float4*)&g_o[((size_t)b * NTOK + p0 + pl) * DD + k0 + ak4]
                : make_float4(0,0,0,0);
            splitf(v.x, Ah[ak4 + 0][pl], Al[ak4 + 0][pl]);
            splitf(v.y, Ah[ak4 + 1][pl], Al[ak4 + 1][pl]);
            splitf(v.z, Ah[ak4 + 2][pl], Al[ak4 + 2][pl]);
            splitf(v.w, Ah[ak4 + 3][pl], Al[ak4 + 3][pl]);
        }
        {
            float4 v = *(const float4*)&w[(size_t)(k0 + bk) * DD + n0 + bn4];
            float4 h4, l4;
            splitf(v.x, h4.x, l4.x); splitf(v.y, h4.y, l4.y);
            splitf(v.z, h4.z, l4.z); splitf(v.w, h4.w, l4.w);
            *(float4*)&Bh[bk][bn4] = h4;
            *(float4*)&Bl[bk][bn4] = l4;
        }
        __syncthreads();

        #pragma unroll
        for (int ktl = 0; ktl < 2; ktl++) {
            unsigned ah[2][4], al[2][4];
            #pragma unroll
            for (int mt = 0; mt < 2; mt++) {
                int mb = wm * 32 + mt * 16;
                ah[mt][0] = __float_as_uint(Ah[ktl*8 + c    ][mb + r    ]);
                ah[mt][1] = __float_as_uint(Ah[ktl*8 + c    ][mb + r + 8]);
                ah[mt][2] = __float_as_uint(Ah[ktl*8 + c + 4][mb + r    ]);
                ah[mt][3] = __float_as_uint(Ah[ktl*8 + c + 4][mb + r + 8]);
                al[mt][0] = __float_as_uint(Al[ktl*8 + c    ][mb + r    ]);
                al[mt][1] = __float_as_uint(Al[ktl*8 + c    ][mb + r + 8]);
                al[mt][2] = __float_as_uint(Al[ktl*8 + c + 4][mb + r    ]);
                al[mt][3] = __float_as_uint(Al[ktl*8 + c + 4][mb + r + 8]);
            }
            #pragma unroll
            for (int nt = 0; nt < 4; nt++) {
                int nb = wn * 32 + nt * 8 + r;
                unsigned bh0 = __float_as_uint(Bh[ktl*8 + c    ][nb]);
                unsigned bh1 = __float_as_uint(Bh[ktl*8 + c + 4][nb]);
                unsigned bl0 = __float_as_uint(Bl[ktl*8 + c    ][nb]);
                unsigned bl1 = __float_as_uint(Bl[ktl*8 + c + 4][nb]);
                #pragma unroll
                for (int mt = 0; mt < 2; mt++)
                    mma3(acc[mt][nt], ah[mt], al[mt], bh0, bh1, bl0, bl1);
            }
        }
        __syncthreads();
    }

    // C -> smem (unioned) -> coalesced transposed store
    #pragma unroll
    for (int mt = 0; mt < 2; mt++) {
        int m = wm * 32 + mt * 16 + r;
        #pragma unroll
        for (int nt = 0; nt < 4; nt++) {
            int n = wn * 32 + nt * 8 + 2 * c;
            Cs[m    ][n    ] = acc[mt][nt].x;
            Cs[m    ][n + 1] = acc[mt][nt].y;
            Cs[m + 8][n    ] = acc[mt][nt].z;
            Cs[m + 8][n + 1] = acc[mt][nt].w;
        }
    }
    __syncthreads();

    #pragma unroll
    for (int it = 0; it < 32; it++) {
        int idx = it * 256 + tid;
        int n = idx >> 7;
        int m = idx & 127;
        int p = p0 + m;
        if (p < NTOK)
            out[((size_t)b * DD + n0 + n) * NTOK + p] = Cs[m][n];
    }
}

// ============================================================
extern "C" void kernel_launch(void* const* d_in, const int* in_sizes, int n_in,
                              void* d_out, int out_size) {
    const float* x          = (const float*)d_in[0];
    const float* w_qkv      = (const float*)d_in[1];
    const float* w_out      = (const float*)d_in[2];
    const float* bias_table = (const float*)d_in[3];
    const int*   rel        = (const int*)d_in[4];
    float* out = (float*)d_out;

    bias_fill<<<(HEADS * NTOK * NTOK + 255) / 256, 256>>>(bias_table, rel);
    qkv_mma<<<dim3(5, 12, BB), 256>>>(x, w_qkv);
    attn_mma<<<dim3(5, BB * HEADS), 256>>>();
    out_mma<<<dim3(5, 4, BB), 256>>>(w_out, out);
}

// round 5
// speedup vs baseline: 1.6782x; 1.6782x over previous
#include <cuda_runtime.h>
#include <math.h>

#define BB    64
#define DD    256
#define HEADS 8
#define DH    32
#define NTOK  625
#define NPAD  640

// ---- scratch (device globals) ----
__device__ float g_q[BB*HEADS*NTOK*DH];
__device__ float g_k[BB*HEADS*NTOK*DH];
__device__ float g_v[BB*HEADS*NTOK*DH];
__device__ float g_bias[HEADS*NPAD*NPAD];
__device__ float g_o[BB*NTOK*DD];

// ================= bf16 split helpers =================
// pack two floats -> bf16x2 word (lo half = x0, hi half = x1)
__device__ __forceinline__ unsigned packbf(float x0, float x1) {
    unsigned u;
    asm("cvt.rn.bf16x2.f32 %0, %1, %2;" : "=r"(u) : "f"(x1), "f"(x0));
    return u;
}
// split pair (x0,x1) into hi word + lo(residual) word
__device__ __forceinline__ void split2(float x0, float x1,
                                       unsigned &h, unsigned &l) {
    h = packbf(x0, x1);
    float h0 = __uint_as_float(h << 16);
    float h1 = __uint_as_float(h & 0xffff0000u);
    l = packbf(x0 - h0, x1 - h1);
}
// m16n8k16 bf16 mma, fp32 accum
__device__ __forceinline__ void mma16(float4 &d, const unsigned a[4],
                                      unsigned b0, unsigned b1) {
    asm volatile(
        "mma.sync.aligned.m16n8k16.row.col.f32.bf16.bf16.f32 "
        "{%0,%1,%2,%3}, {%4,%5,%6,%7}, {%8,%9}, {%0,%1,%2,%3};"
        : "+f"(d.x), "+f"(d.y), "+f"(d.z), "+f"(d.w)
        : "r"(a[0]), "r"(a[1]), "r"(a[2]), "r"(a[3]), "r"(b0), "r"(b1));
}
// 3-term: ah*bh + ah*bl + al*bh
__device__ __forceinline__ void mma3(float4 &d, const unsigned ah[4],
                                     const unsigned al[4],
                                     unsigned bh0, unsigned bh1,
                                     unsigned bl0, unsigned bl1) {
    mma16(d, ah, bh0, bh1);
    mma16(d, ah, bl0, bl1);
    mma16(d, al, bh0, bh1);
}

// ============================================================
// Kernel 0: bias_fill (j-stride padded to 640)
// ============================================================
__global__ void bias_fill(const float* __restrict__ table,
                          const int*   __restrict__ rel) {
    int idx = blockIdx.x * blockDim.x + threadIdx.x;
    const int total = HEADS * NTOK * NTOK;
    if (idx >= total) return;
    int h = idx / (NTOK * NTOK);
    int r = idx - h * (NTOK * NTOK);
    int i = r / NTOK;
    int j = r - i * NTOK;
    g_bias[(h * NPAD + i) * NPAD + j] = table[rel[r] * HEADS + h];
}

// ============================================================
// Kernel 1: QKV projection, bf16 3-mma. 128(M)x64(N), K=256,
// staged 32 k at a time. Smem holds bf16x2 words: A[m][k2], B[n][k2].
// ============================================================
__global__ __launch_bounds__(256) void qkv_mma(const float* __restrict__ x,
                                               const float* __restrict__ w) {
    __shared__ unsigned Ah[128][17], Al[128][17];   // 16 words + pad
    __shared__ unsigned Bh[64][17],  Bl[64][17];

    int b  = blockIdx.z;
    int p0 = blockIdx.x * 128;
    int n0 = blockIdx.y * 64;
    int tid = threadIdx.x;
    int wid = tid >> 5, lane = tid & 31;
    int wm = wid & 3, wn = wid >> 2;
    int r = lane >> 2, c = lane & 3;
    const float* xb = x + (size_t)b * DD * NTOK;

    float4 acc[2][4];
    #pragma unroll
    for (int i = 0; i < 2; i++)
        #pragma unroll
        for (int j = 0; j < 4; j++) acc[i][j] = make_float4(0,0,0,0);

    int am   = tid & 127;        // A: m row
    int ahlf = tid >> 7;         // 0/1 -> words 0..7 / 8..15
    int bn   = tid & 63;         // B: n row
    int bq   = tid >> 6;         // 0..3 -> words 4q..4q+3
    bool ap_ok = (p0 + am) < NTOK;

    for (int k0 = 0; k0 < DD; k0 += 32) {
        #pragma unroll
        for (int wd = 0; wd < 8; wd++) {
            int k = k0 + 16 * ahlf + 2 * wd;
            float f0 = ap_ok ? xb[(size_t)k * NTOK + p0 + am] : 0.f;
            float f1 = ap_ok ? xb[(size_t)(k + 1) * NTOK + p0 + am] : 0.f;
            split2(f0, f1, Ah[am][8*ahlf + wd], Al[am][8*ahlf + wd]);
        }
        #pragma unroll
        for (int wd = 0; wd < 4; wd++) {
            int k = k0 + 8 * bq + 2 * wd;
            float f0 = w[(size_t)k * (3*DD) + n0 + bn];
            float f1 = w[(size_t)(k + 1) * (3*DD) + n0 + bn];
            split2(f0, f1, Bh[bn][4*bq + wd], Bl[bn][4*bq + wd]);
        }
        __syncthreads();

        #pragma unroll
        for (int ktl = 0; ktl < 2; ktl++) {
            unsigned ah[2][4], al[2][4];
            #pragma unroll
            for (int mt = 0; mt < 2; mt++) {
                int mb = wm * 32 + mt * 16;
                ah[mt][0] = Ah[mb + r    ][ktl*8 + c    ];
                ah[mt][1] = Ah[mb + r + 8][ktl*8 + c    ];
                ah[mt][2] = Ah[mb + r    ][ktl*8 + c + 4];
                ah[mt][3] = Ah[mb + r + 8][ktl*8 + c + 4];
                al[mt][0] = Al[mb + r    ][ktl*8 + c    ];
                al[mt][1] = Al[mb + r + 8][ktl*8 + c    ];
                al[mt][2] = Al[mb + r    ][ktl*8 + c + 4];
                al[mt][3] = Al[mb + r + 8][ktl*8 + c + 4];
            }
            #pragma unroll
            for (int nt = 0; nt < 4; nt++) {
                int nb = wn * 32 + nt * 8 + r;
                unsigned bh0 = Bh[nb][ktl*8 + c    ];
                unsigned bh1 = Bh[nb][ktl*8 + c + 4];
                unsigned bl0 = Bl[nb][ktl*8 + c    ];
                unsigned bl1 = Bl[nb][ktl*8 + c + 4];
                #pragma unroll
                for (int mt = 0; mt < 2; mt++)
                    mma3(acc[mt][nt], ah[mt], al[mt], bh0, bh1, bl0, bl1);
            }
        }
        __syncthreads();
    }

    // epilogue: scatter to g_q/g_k/g_v (bh, p, e); q pre-scaled
    #pragma unroll
    for (int nt = 0; nt < 4; nt++) {
        int ng0 = n0 + wn * 32 + nt * 8 + 2 * c;
        int which = ng0 >> 8;
        int h = (ng0 >> 5) & 7;
        int e = ng0 & 31;
        float* dst = (which == 0) ? g_q : (which == 1) ? g_k : g_v;
        float s = (which == 0) ? 0.17677669529663687f : 1.f;
        size_t base = (size_t)(b * HEADS + h) * NTOK * DH + e;
        #pragma unroll
        for (int mt = 0; mt < 2; mt++) {
            int p = p0 + wm * 32 + mt * 16 + r;
            if (p < NTOK)
                *(float2*)&dst[base + (size_t)p * DH] =
                    make_float2(acc[mt][nt].x * s, acc[mt][nt].y * s);
            if (p + 8 < NTOK)
                *(float2*)&dst[base + (size_t)(p + 8) * DH] =
                    make_float2(acc[mt][nt].z * s, acc[mt][nt].w * s);
        }
    }
}

// ============================================================
// Kernel 2: flash attention, bf16 3-mma, P register-resident.
// Block = 128 queries x one (b,h), 8 warps, 16 q-rows each.
// K smem [j][e-pairs]; V smem transposed [e][j-pairs].
// ============================================================
__global__ __launch_bounds__(256) void attn_mma() {
    __shared__ unsigned Kh[64][17], Kl[64][17];   // [j][e2] bf16x2 words
    __shared__ unsigned Vh[32][36], Vl[32][36];   // [e][j2] words, stride 36

    int tid = threadIdx.x;
    int wid = tid >> 5, lane = tid & 31;
    int r = lane >> 2, c = lane & 3;

    int q0 = blockIdx.x * 128;
    int bh = blockIdx.y;
    int h = bh & 7;
    const float* qb = g_q + (size_t)bh * NTOK * DH;
    const float* kb = g_k + (size_t)bh * NTOK * DH;
    const float* vb = g_v + (size_t)bh * NTOK * DH;

    // Q fragments (2 k16 steps over DH=32), pre-split bf16, register-resident
    unsigned qh[2][4], ql[2][4];
    int pr = q0 + wid * 16 + r;
    #pragma unroll
    for (int kt = 0; kt < 2; kt++) {
        float2 q00 = (pr < NTOK)
            ? *(const float2*)&qb[(size_t)pr * DH + kt*16 + 2*c]
            : make_float2(0,0);
        float2 q01 = (pr < NTOK)
            ? *(const float2*)&qb[(size_t)pr * DH + kt*16 + 2*c + 8]
            : make_float2(0,0);
        float2 q10 = (pr + 8 < NTOK)
            ? *(const float2*)&qb[(size_t)(pr+8) * DH + kt*16 + 2*c]
            : make_float2(0,0);
        float2 q11 = (pr + 8 < NTOK)
            ? *(const float2*)&qb[(size_t)(pr+8) * DH + kt*16 + 2*c + 8]
            : make_float2(0,0);
        split2(q00.x, q00.y, qh[kt][0], ql[kt][0]);
        split2(q10.x, q10.y, qh[kt][1], ql[kt][1]);
        split2(q01.x, q01.y, qh[kt][2], ql[kt][2]);
        split2(q11.x, q11.y, qh[kt][3], ql[kt][3]);
    }

    float4 O[4];
    #pragma unroll
    for (int i = 0; i < 4; i++) O[i] = make_float4(0,0,0,0);
    float m0 = -INFINITY, m1 = -INFINITY, l0 = 0.f, l1 = 0.f;

    for (int jt = 0; jt < 10; jt++) {
        int j0 = jt * 64;
        // ---- stage K [j][e2] ----
        {
            int row = tid >> 2, e0 = (tid & 3) * 8;
            int jp = j0 + row;
            float kv[8];
            if (jp < NTOK) {
                *(float4*)&kv[0] = *(const float4*)&kb[(size_t)jp * DH + e0];
                *(float4*)&kv[4] = *(const float4*)&kb[(size_t)jp * DH + e0 + 4];
            } else {
                #pragma unroll
                for (int i = 0; i < 8; i++) kv[i] = 0.f;
            }
            #pragma unroll
            for (int i = 0; i < 4; i++)
                split2(kv[2*i], kv[2*i+1],
                       Kh[row][(e0 >> 1) + i], Kl[row][(e0 >> 1) + i]);
        }
        // ---- stage V transposed [e][j2] ----
        {
            int j2 = tid & 31, e0 = (tid >> 5) * 4;
            int ja = j0 + 2*j2, jb = ja + 1;
            float v0[4], v1[4];
            if (ja < NTOK) *(float4*)v0 = *(const float4*)&vb[(size_t)ja * DH + e0];
            else { v0[0]=v0[1]=v0[2]=v0[3]=0.f; }
            if (jb < NTOK) *(float4*)v1 = *(const float4*)&vb[(size_t)jb * DH + e0];
            else { v1[0]=v1[1]=v1[2]=v1[3]=0.f; }
            #pragma unroll
            for (int i = 0; i < 4; i++)
                split2(v0[i], v1[i], Vh[e0 + i][j2], Vl[e0 + i][j2]);
        }
        __syncthreads();

        // ---- S = Q K^T ----
        float4 acc[8];
        #pragma unroll
        for (int i = 0; i < 8; i++) acc[i] = make_float4(0,0,0,0);
        #pragma unroll
        for (int kt = 0; kt < 2; kt++) {
            #pragma unroll
            for (int nt = 0; nt < 8; nt++) {
                unsigned bh0 = Kh[nt*8 + r][kt*8 + c    ];
                unsigned bh1 = Kh[nt*8 + r][kt*8 + c + 4];
                unsigned bl0 = Kl[nt*8 + r][kt*8 + c    ];
                unsigned bl1 = Kl[nt*8 + r][kt*8 + c + 4];
                mma3(acc[nt], qh[kt], ql[kt], bh0, bh1, bl0, bl1);
            }
        }

        // ---- bias + tail mask ----
        {
            const float* bp = g_bias + ((size_t)(h * NPAD + q0 + wid*16 + r)) * NPAD + j0;
            #pragma unroll
            for (int nt = 0; nt < 8; nt++) {
                float2 b0v = *(const float2*)&bp[nt*8 + 2*c];
                float2 b1v = *(const float2*)&bp[8*NPAD + nt*8 + 2*c];
                acc[nt].x += b0v.x; acc[nt].y += b0v.y;
                acc[nt].z += b1v.x; acc[nt].w += b1v.y;
            }
            if (j0 + 64 > NTOK) {
                #pragma unroll
                for (int nt = 0; nt < 8; nt++) {
                    int jc = j0 + nt*8 + 2*c;
                    if (jc     >= NTOK) { acc[nt].x = -1e30f; acc[nt].z = -1e30f; }
                    if (jc + 1 >= NTOK) { acc[nt].y = -1e30f; acc[nt].w = -1e30f; }
                }
            }
        }

        // ---- online softmax (quad reduce) ----
        float t0 = -INFINITY, t1 = -INFINITY;
        #pragma unroll
        for (int nt = 0; nt < 8; nt++) {
            t0 = fmaxf(t0, fmaxf(acc[nt].x, acc[nt].y));
            t1 = fmaxf(t1, fmaxf(acc[nt].z, acc[nt].w));
        }
        #pragma unroll
        for (int off = 1; off <= 2; off <<= 1) {
            t0 = fmaxf(t0, __shfl_xor_sync(0xffffffffu, t0, off));
            t1 = fmaxf(t1, __shfl_xor_sync(0xffffffffu, t1, off));
        }
        float mn0 = fmaxf(m0, t0), mn1 = fmaxf(m1, t1);
        float cor0 = __expf(m0 - mn0), cor1 = __expf(m1 - mn1);
        float s0 = 0.f, s1 = 0.f;
        #pragma unroll
        for (int nt = 0; nt < 8; nt++) {
            acc[nt].x = __expf(acc[nt].x - mn0);
            acc[nt].y = __expf(acc[nt].y - mn0);
            acc[nt].z = __expf(acc[nt].z - mn1);
            acc[nt].w = __expf(acc[nt].w - mn1);
            s0 += acc[nt].x + acc[nt].y;
            s1 += acc[nt].z + acc[nt].w;
        }
        #pragma unroll
        for (int off = 1; off <= 2; off <<= 1) {
            s0 += __shfl_xor_sync(0xffffffffu, s0, off);
            s1 += __shfl_xor_sync(0xffffffffu, s1, off);
        }
        l0 = l0 * cor0 + s0;  m0 = mn0;
        l1 = l1 * cor1 + s1;  m1 = mn1;
        #pragma unroll
        for (int i = 0; i < 4; i++) {
            O[i].x *= cor0; O[i].y *= cor0;
            O[i].z *= cor1; O[i].w *= cor1;
        }

        // ---- O += P V, P register-resident (C-layout == A-layout) ----
        #pragma unroll
        for (int kt = 0; kt < 4; kt++) {
            unsigned ph[4], pl[4];
            split2(acc[2*kt  ].x, acc[2*kt  ].y, ph[0], pl[0]);
            split2(acc[2*kt  ].z, acc[2*kt  ].w, ph[1], pl[1]);
            split2(acc[2*kt+1].x, acc[2*kt+1].y, ph[2], pl[2]);
            split2(acc[2*kt+1].z, acc[2*kt+1].w, ph[3], pl[3]);
            #pragma unroll
            for (int nt = 0; nt < 4; nt++) {
                unsigned bh0 = Vh[nt*8 + r][kt*8 + c    ];
                unsigned bh1 = Vh[nt*8 + r][kt*8 + c + 4];
                unsigned bl0 = Vl[nt*8 + r][kt*8 + c    ];
                unsigned bl1 = Vl[nt*8 + r][kt*8 + c + 4];
                mma3(O[nt], ph, pl, bh0, bh1, bl0, bl1);
            }
        }
        __syncthreads();
    }

    // epilogue
    float inv0 = 1.f / l0, inv1 = 1.f / l1;
    float* ob = g_o + (size_t)(bh >> 3) * NTOK * DD + h * DH;
    #pragma unroll
    for (int nt = 0; nt < 4; nt++) {
        int e = nt*8 + 2*c;
        int p = q0 + wid*16 + r;
        if (p < NTOK)
            *(float2*)&ob[(size_t)p * DD + e] =
                make_float2(O[nt].x * inv0, O[nt].y * inv0);
        if (p + 8 < NTOK)
            *(float2*)&ob[(size_t)(p + 8) * DD + e] =
                make_float2(O[nt].z * inv1, O[nt].w * inv1);
    }
}

// ============================================================
// Kernel 3: output projection, bf16 3-mma + transposed store.
// ============================================================
#define OUT_CS_WORDS (128*69)                  // 8832 (>= AB words 6528)
#define OUT_SM_WORDS OUT_CS_WORDS

__global__ __launch_bounds__(256) void out_mma(const float* __restrict__ w,
                                               float* __restrict__ out) {
    __shared__ __align__(16) unsigned smbuf[OUT_SM_WORDS];
    unsigned (*Ah)[17] = (unsigned(*)[17])smbuf;
    unsigned (*Al)[17] = (unsigned(*)[17])(smbuf + 128*17);
    unsigned (*Bh)[17] = (unsigned(*)[17])(smbuf + 2*128*17);
    unsigned (*Bl)[17] = (unsigned(*)[17])(smbuf + 2*128*17 + 64*17);
    float    (*Cs)[69] = (float(*)[69])smbuf;

    int b  = blockIdx.z;
    int p0 = blockIdx.x * 128;
    int n0 = blockIdx.y * 64;
    int tid = threadIdx.x;
    int wid = tid >> 5, lane = tid & 31;
    int wm = wid & 3, wn = wid >> 2;
    int r = lane >> 2, c = lane & 3;

    float4 acc[2][4];
    #pragma unroll
    for (int i = 0; i < 2; i++)
        #pragma unroll
        for (int j = 0; j < 4; j++) acc[i][j] = make_float4(0,0,0,0);

    int am   = tid >> 1;        // A: m row (g_o k-contiguous)
    int ahlf = tid & 1;         // words 0..7 / 8..15
    int bn   = tid & 63;
    int bq   = tid >> 6;
    bool ap_ok = (p0 + am) < NTOK;

    for (int k0 = 0; k0 < DD; k0 += 32) {
        {
            // FIX (R4 bug): each (am, ahlf) covers 16 k = 8 words; load all 16 floats.
            float av[16];
            if (ap_ok) {
                const float* src = &g_o[((size_t)b * NTOK + p0 + am) * DD + k0 + 16*ahlf];
                *(float4*)&av[0]  = *(const float4*)&src[0];
                *(float4*)&av[4]  = *(const float4*)&src[4];
                *(float4*)&av[8]  = *(const float4*)&src[8];
                *(float4*)&av[12] = *(const float4*)&src[12];
            } else {
                #pragma unroll
                for (int i = 0; i < 16; i++) av[i] = 0.f;
            }
            #pragma unroll
            for (int i = 0; i < 8; i++)
                split2(av[2*i], av[2*i+1],
                       Ah[am][8*ahlf + i], Al[am][8*ahlf + i]);
        }
        #pragma unroll
        for (int wd = 0; wd < 4; wd++) {
            int k = k0 + 8 * bq + 2 * wd;
            float f0 = w[(size_t)k * DD + n0 + bn];
            float f1 = w[(size_t)(k + 1) * DD + n0 + bn];
            split2(f0, f1, Bh[bn][4*bq + wd], Bl[bn][4*bq + wd]);
        }
        __syncthreads();

        #pragma unroll
        for (int ktl = 0; ktl < 2; ktl++) {
            unsigned ah[2][4], al[2][4];
            #pragma unroll
            for (int mt = 0; mt < 2; mt++) {
                int mb = wm * 32 + mt * 16;
                ah[mt][0] = Ah[mb + r    ][ktl*8 + c    ];
                ah[mt][1] = Ah[mb + r + 8][ktl*8 + c    ];
                ah[mt][2] = Ah[mb + r    ][ktl*8 + c + 4];
                ah[mt][3] = Ah[mb + r + 8][ktl*8 + c + 4];
                al[mt][0] = Al[mb + r    ][ktl*8 + c    ];
                al[mt][1] = Al[mb + r + 8][ktl*8 + c    ];
                al[mt][2] = Al[mb + r    ][ktl*8 + c + 4];
                al[mt][3] = Al[mb + r + 8][ktl*8 + c + 4];
            }
            #pragma unroll
            for (int nt = 0; nt < 4; nt++) {
                int nb = wn * 32 + nt * 8 + r;
                unsigned bh0 = Bh[nb][ktl*8 + c    ];
                unsigned bh1 = Bh[nb][ktl*8 + c + 4];
                unsigned bl0 = Bl[nb][ktl*8 + c    ];
                unsigned bl1 = Bl[nb][ktl*8 + c + 4];
                #pragma unroll
                for (int mt = 0; mt < 2; mt++)
                    mma3(acc[mt][nt], ah[mt], al[mt], bh0, bh1, bl0, bl1);
            }
        }
        __syncthreads();
    }

    // C -> smem (unioned) -> coalesced transposed store
    #pragma unroll
    for (int mt = 0; mt < 2; mt++) {
        int m = wm * 32 + mt * 16 + r;
        #pragma unroll
        for (int nt = 0; nt < 4; nt++) {
            int n = wn * 32 + nt * 8 + 2 * c;
            Cs[m    ][n    ] = acc[mt][nt].x;
            Cs[m    ][n + 1] = acc[mt][nt].y;
            Cs[m + 8][n    ] = acc[mt][nt].z;
            Cs[m + 8][n + 1] = acc[mt][nt].w;
        }
    }
    __syncthreads();

    #pragma unroll
    for (int it = 0; it < 32; it++) {
        int idx = it * 256 + tid;
        int n = idx >> 7;
        int m = idx & 127;
        int p = p0 + m;
        if (p < NTOK)
            out[((size_t)b * DD + n0 + n) * NTOK + p] = Cs[m][n];
    }
}

// ============================================================
extern "C" void kernel_launch(void* const* d_in, const int* in_sizes, int n_in,
                              void* d_out, int out_size) {
    const float* x          = (const float*)d_in[0];
    const float* w_qkv      = (const float*)d_in[1];
    const float* w_out      = (const float*)d_in[2];
    const float* bias_table = (const float*)d_in[3];
    const int*   rel        = (const int*)d_in[4];
    float* out = (float*)d_out;

    bias_fill<<<(HEADS * NTOK * NTOK + 255) / 256, 256>>>(bias_table, rel);
    qkv_mma<<<dim3(5, 12, BB), 256>>>(x, w_qkv);
    attn_mma<<<dim3(5, BB * HEADS), 256>>>();
    out_mma<<<dim3(5, 4, BB), 256>>>(w_out, out);
}

// round 6
// speedup vs baseline: 2.0027x; 1.1934x over previous
#include <cuda_runtime.h>
#include <math.h>

#define BB    64
#define DD    256
#define HEADS 8
#define DH    32
#define NTOK  625
#define NPAD  640

// ---- scratch (device globals) ----
__device__ float g_q[BB*HEADS*NTOK*DH];
__device__ float g_k[BB*HEADS*NTOK*DH];
__device__ float g_v[BB*HEADS*NTOK*DH];
__device__ float g_bias[HEADS*NPAD*NPAD];
__device__ float g_o[BB*NTOK*DD];

// ================= bf16 split helpers =================
__device__ __forceinline__ unsigned packbf(float x0, float x1) {
    unsigned u;
    asm("cvt.rn.bf16x2.f32 %0, %1, %2;" : "=r"(u) : "f"(x1), "f"(x0));
    return u;
}
__device__ __forceinline__ void split2(float x0, float x1,
                                       unsigned &h, unsigned &l) {
    h = packbf(x0, x1);
    float h0 = __uint_as_float(h << 16);
    float h1 = __uint_as_float(h & 0xffff0000u);
    l = packbf(x0 - h0, x1 - h1);
}
__device__ __forceinline__ void mma16(float4 &d, const unsigned a[4],
                                      unsigned b0, unsigned b1) {
    asm volatile(
        "mma.sync.aligned.m16n8k16.row.col.f32.bf16.bf16.f32 "
        "{%0,%1,%2,%3}, {%4,%5,%6,%7}, {%8,%9}, {%0,%1,%2,%3};"
        : "+f"(d.x), "+f"(d.y), "+f"(d.z), "+f"(d.w)
        : "r"(a[0]), "r"(a[1]), "r"(a[2]), "r"(a[3]), "r"(b0), "r"(b1));
}
__device__ __forceinline__ void mma3(float4 &d, const unsigned ah[4],
                                     const unsigned al[4],
                                     unsigned bh0, unsigned bh1,
                                     unsigned bl0, unsigned bl1) {
    mma16(d, ah, bh0, bh1);
    mma16(d, ah, bl0, bl1);
    mma16(d, al, bh0, bh1);
}
// ================= ldmatrix helpers =================
__device__ __forceinline__ unsigned sptr(const void* p) {
    return (unsigned)__cvta_generic_to_shared(p);
}
__device__ __forceinline__ void ldsm4(unsigned r[4], unsigned addr) {
    asm volatile("ldmatrix.sync.aligned.m8n8.x4.shared.b16 {%0,%1,%2,%3}, [%4];"
        : "=r"(r[0]), "=r"(r[1]), "=r"(r[2]), "=r"(r[3]) : "r"(addr));
}

// ============================================================
// Kernel 0: bias_fill (j-stride padded to 640)
// ============================================================
__global__ void bias_fill(const float* __restrict__ table,
                          const int*   __restrict__ rel) {
    int idx = blockIdx.x * blockDim.x + threadIdx.x;
    const int total = HEADS * NTOK * NTOK;
    if (idx >= total) return;
    int h = idx / (NTOK * NTOK);
    int r = idx - h * (NTOK * NTOK);
    int i = r / NTOK;
    int j = r - i * NTOK;
    g_bias[(h * NPAD + i) * NPAD + j] = table[rel[r] * HEADS + h];
}

// ============================================================
// Kernel 1: QKV projection, bf16 3-mma + LDSM. 128x64, K=256,
// 32 k staged per iter. Tiles: words [row][20] (16 used, 16B rows,
// 5m mod 8 bank-group walk -> conflict-free LDSM).
// ============================================================
__global__ __launch_bounds__(256) void qkv_mma(const float* __restrict__ x,
                                               const float* __restrict__ w) {
    __shared__ __align__(16) unsigned Ah[128][20], Al[128][20];
    __shared__ __align__(16) unsigned Bh[64][20],  Bl[64][20];

    int b  = blockIdx.z;
    int p0 = blockIdx.x * 128;
    int n0 = blockIdx.y * 64;
    int tid = threadIdx.x;
    int wid = tid >> 5, lane = tid & 31;
    int wm = wid & 3, wn = wid >> 2;
    int r = lane >> 2, c = lane & 3;
    const float* xb = x + (size_t)b * DD * NTOK;

    float4 acc[2][4];
    #pragma unroll
    for (int i = 0; i < 2; i++)
        #pragma unroll
        for (int j = 0; j < 4; j++) acc[i][j] = make_float4(0,0,0,0);

    int am   = tid & 127;
    int ahlf = tid >> 7;
    int bn   = tid & 63;
    int bq   = tid >> 6;
    bool ap_ok = (p0 + am) < NTOK;

    // LDSM lane->address components
    int aRow = lane & 15;
    int aSel = (lane >> 4) * 4;
    int bRow = ((lane >> 4) << 3) | (lane & 7);
    int bSel = ((lane >> 3) & 1) * 4;
    unsigned AhB = sptr(Ah), AlB = sptr(Al), BhB = sptr(Bh), BlB = sptr(Bl);

    for (int k0 = 0; k0 < DD; k0 += 32) {
        #pragma unroll
        for (int wd = 0; wd < 8; wd++) {
            int k = k0 + 16 * ahlf + 2 * wd;
            float f0 = ap_ok ? xb[(size_t)k * NTOK + p0 + am] : 0.f;
            float f1 = ap_ok ? xb[(size_t)(k + 1) * NTOK + p0 + am] : 0.f;
            split2(f0, f1, Ah[am][8*ahlf + wd], Al[am][8*ahlf + wd]);
        }
        #pragma unroll
        for (int wd = 0; wd < 4; wd++) {
            int k = k0 + 8 * bq + 2 * wd;
            float f0 = w[(size_t)k * (3*DD) + n0 + bn];
            float f1 = w[(size_t)(k + 1) * (3*DD) + n0 + bn];
            split2(f0, f1, Bh[bn][4*bq + wd], Bl[bn][4*bq + wd]);
        }
        __syncthreads();

        #pragma unroll
        for (int ktl = 0; ktl < 2; ktl++) {
            unsigned ah[2][4], al[2][4];
            #pragma unroll
            for (int mt = 0; mt < 2; mt++) {
                unsigned off = ((wm*32 + mt*16 + aRow) * 20 + ktl*8 + aSel) * 4u;
                ldsm4(ah[mt], AhB + off);
                ldsm4(al[mt], AlB + off);
            }
            unsigned bhf[4][2], blf[4][2];
            #pragma unroll
            for (int ntp = 0; ntp < 2; ntp++) {
                unsigned off = ((wn*32 + ntp*16 + bRow) * 20 + ktl*8 + bSel) * 4u;
                unsigned t[4];
                ldsm4(t, BhB + off);
                bhf[2*ntp][0] = t[0]; bhf[2*ntp][1] = t[1];
                bhf[2*ntp+1][0] = t[2]; bhf[2*ntp+1][1] = t[3];
                ldsm4(t, BlB + off);
                blf[2*ntp][0] = t[0]; blf[2*ntp][1] = t[1];
                blf[2*ntp+1][0] = t[2]; blf[2*ntp+1][1] = t[3];
            }
            #pragma unroll
            for (int nt = 0; nt < 4; nt++)
                #pragma unroll
                for (int mt = 0; mt < 2; mt++)
                    mma3(acc[mt][nt], ah[mt], al[mt],
                         bhf[nt][0], bhf[nt][1], blf[nt][0], blf[nt][1]);
        }
        __syncthreads();
    }

    // epilogue: scatter to g_q/g_k/g_v (bh, p, e); q pre-scaled
    #pragma unroll
    for (int nt = 0; nt < 4; nt++) {
        int ng0 = n0 + wn * 32 + nt * 8 + 2 * c;
        int which = ng0 >> 8;
        int h = (ng0 >> 5) & 7;
        int e = ng0 & 31;
        float* dst = (which == 0) ? g_q : (which == 1) ? g_k : g_v;
        float s = (which == 0) ? 0.17677669529663687f : 1.f;
        size_t base = (size_t)(b * HEADS + h) * NTOK * DH + e;
        #pragma unroll
        for (int mt = 0; mt < 2; mt++) {
            int p = p0 + wm * 32 + mt * 16 + r;
            if (p < NTOK)
                *(float2*)&dst[base + (size_t)p * DH] =
                    make_float2(acc[mt][nt].x * s, acc[mt][nt].y * s);
            if (p + 8 < NTOK)
                *(float2*)&dst[base + (size_t)(p + 8) * DH] =
                    make_float2(acc[mt][nt].z * s, acc[mt][nt].w * s);
        }
    }
}

// ============================================================
// Kernel 2: flash attention, bf16 3-mma + LDSM, P register-resident.
// K tile [j][20 words]; V tile transposed [e][36 words] (both
// 16B rows, conflict-free LDSM walks).
// ============================================================
__global__ __launch_bounds__(256) void attn_mma() {
    __shared__ __align__(16) unsigned Kh[64][20], Kl[64][20];
    __shared__ __align__(16) unsigned Vh[32][36], Vl[32][36];

    int tid = threadIdx.x;
    int wid = tid >> 5, lane = tid & 31;
    int r = lane >> 2, c = lane & 3;

    int q0 = blockIdx.x * 128;
    int bh = blockIdx.y;
    int h = bh & 7;
    const float* qb = g_q + (size_t)bh * NTOK * DH;
    const float* kb = g_k + (size_t)bh * NTOK * DH;
    const float* vb = g_v + (size_t)bh * NTOK * DH;

    int bRow = ((lane >> 4) << 3) | (lane & 7);
    int bSel = ((lane >> 3) & 1) * 4;
    unsigned KhB = sptr(Kh), KlB = sptr(Kl), VhB = sptr(Vh), VlB = sptr(Vl);

    // Q fragments (2 k16 over DH=32), pre-split, register-resident
    unsigned qh[2][4], ql[2][4];
    int pr = q0 + wid * 16 + r;
    #pragma unroll
    for (int kt = 0; kt < 2; kt++) {
        float2 q00 = (pr < NTOK)
            ? *(const float2*)&qb[(size_t)pr * DH + kt*16 + 2*c]
            : make_float2(0,0);
        float2 q01 = (pr < NTOK)
            ? *(const float2*)&qb[(size_t)pr * DH + kt*16 + 2*c + 8]
            : make_float2(0,0);
        float2 q10 = (pr + 8 < NTOK)
            ? *(const float2*)&qb[(size_t)(pr+8) * DH + kt*16 + 2*c]
            : make_float2(0,0);
        float2 q11 = (pr + 8 < NTOK)
            ? *(const float2*)&qb[(size_t)(pr+8) * DH + kt*16 + 2*c + 8]
            : make_float2(0,0);
        split2(q00.x, q00.y, qh[kt][0], ql[kt][0]);
        split2(q10.x, q10.y, qh[kt][1], ql[kt][1]);
        split2(q01.x, q01.y, qh[kt][2], ql[kt][2]);
        split2(q11.x, q11.y, qh[kt][3], ql[kt][3]);
    }

    float4 O[4];
    #pragma unroll
    for (int i = 0; i < 4; i++) O[i] = make_float4(0,0,0,0);
    float m0 = -INFINITY, m1 = -INFINITY, l0 = 0.f, l1 = 0.f;

    for (int jt = 0; jt < 10; jt++) {
        int j0 = jt * 64;
        // ---- stage K [j][e2] ----
        {
            int row = tid >> 2, e0 = (tid & 3) * 8;
            int jp = j0 + row;
            float kv[8];
            if (jp < NTOK) {
                *(float4*)&kv[0] = *(const float4*)&kb[(size_t)jp * DH + e0];
                *(float4*)&kv[4] = *(const float4*)&kb[(size_t)jp * DH + e0 + 4];
            } else {
                #pragma unroll
                for (int i = 0; i < 8; i++) kv[i] = 0.f;
            }
            #pragma unroll
            for (int i = 0; i < 4; i++)
                split2(kv[2*i], kv[2*i+1],
                       Kh[row][(e0 >> 1) + i], Kl[row][(e0 >> 1) + i]);
        }
        // ---- stage V transposed [e][j2] ----
        {
            int j2 = tid & 31, e0 = (tid >> 5) * 4;
            int ja = j0 + 2*j2, jb = ja + 1;
            float v0[4], v1[4];
            if (ja < NTOK) *(float4*)v0 = *(const float4*)&vb[(size_t)ja * DH + e0];
            else { v0[0]=v0[1]=v0[2]=v0[3]=0.f; }
            if (jb < NTOK) *(float4*)v1 = *(const float4*)&vb[(size_t)jb * DH + e0];
            else { v1[0]=v1[1]=v1[2]=v1[3]=0.f; }
            #pragma unroll
            for (int i = 0; i < 4; i++)
                split2(v0[i], v1[i], Vh[e0 + i][j2], Vl[e0 + i][j2]);
        }
        __syncthreads();

        // ---- S = Q K^T (LDSM on K) ----
        float4 acc[8];
        #pragma unroll
        for (int i = 0; i < 8; i++) acc[i] = make_float4(0,0,0,0);
        #pragma unroll
        for (int kt = 0; kt < 2; kt++) {
            #pragma unroll
            for (int ntp = 0; ntp < 4; ntp++) {
                unsigned off = ((ntp*16 + bRow) * 20 + kt*8 + bSel) * 4u;
                unsigned th[4], tl[4];
                ldsm4(th, KhB + off);
                ldsm4(tl, KlB + off);
                mma3(acc[2*ntp  ], qh[kt], ql[kt], th[0], th[1], tl[0], tl[1]);
                mma3(acc[2*ntp+1], qh[kt], ql[kt], th[2], th[3], tl[2], tl[3]);
            }
        }

        // ---- bias + tail mask ----
        {
            const float* bp = g_bias + ((size_t)(h * NPAD + q0 + wid*16 + r)) * NPAD + j0;
            #pragma unroll
            for (int nt = 0; nt < 8; nt++) {
                float2 b0v = *(const float2*)&bp[nt*8 + 2*c];
                float2 b1v = *(const float2*)&bp[8*NPAD + nt*8 + 2*c];
                acc[nt].x += b0v.x; acc[nt].y += b0v.y;
                acc[nt].z += b1v.x; acc[nt].w += b1v.y;
            }
            if (j0 + 64 > NTOK) {
                #pragma unroll
                for (int nt = 0; nt < 8; nt++) {
                    int jc = j0 + nt*8 + 2*c;
                    if (jc     >= NTOK) { acc[nt].x = -1e30f; acc[nt].z = -1e30f; }
                    if (jc + 1 >= NTOK) { acc[nt].y = -1e30f; acc[nt].w = -1e30f; }
                }
            }
        }

        // ---- online softmax (quad reduce) ----
        float t0 = -INFINITY, t1 = -INFINITY;
        #pragma unroll
        for (int nt = 0; nt < 8; nt++) {
            t0 = fmaxf(t0, fmaxf(acc[nt].x, acc[nt].y));
            t1 = fmaxf(t1, fmaxf(acc[nt].z, acc[nt].w));
        }
        #pragma unroll
        for (int off = 1; off <= 2; off <<= 1) {
            t0 = fmaxf(t0, __shfl_xor_sync(0xffffffffu, t0, off));
            t1 = fmaxf(t1, __shfl_xor_sync(0xffffffffu, t1, off));
        }
        float mn0 = fmaxf(m0, t0), mn1 = fmaxf(m1, t1);
        float cor0 = __expf(m0 - mn0), cor1 = __expf(m1 - mn1);
        float s0 = 0.f, s1 = 0.f;
        #pragma unroll
        for (int nt = 0; nt < 8; nt++) {
            acc[nt].x = __expf(acc[nt].x - mn0);
            acc[nt].y = __expf(acc[nt].y - mn0);
            acc[nt].z = __expf(acc[nt].z - mn1);
            acc[nt].w = __expf(acc[nt].w - mn1);
            s0 += acc[nt].x + acc[nt].y;
            s1 += acc[nt].z + acc[nt].w;
        }
        #pragma unroll
        for (int off = 1; off <= 2; off <<= 1) {
            s0 += __shfl_xor_sync(0xffffffffu, s0, off);
            s1 += __shfl_xor_sync(0xffffffffu, s1, off);
        }
        l0 = l0 * cor0 + s0;  m0 = mn0;
        l1 = l1 * cor1 + s1;  m1 = mn1;
        #pragma unroll
        for (int i = 0; i < 4; i++) {
            O[i].x *= cor0; O[i].y *= cor0;
            O[i].z *= cor1; O[i].w *= cor1;
        }

        // ---- O += P V (LDSM on V; P register-resident) ----
        #pragma unroll
        for (int kt = 0; kt < 4; kt++) {
            unsigned ph[4], pl[4];
            split2(acc[2*kt  ].x, acc[2*kt  ].y, ph[0], pl[0]);
            split2(acc[2*kt  ].z, acc[2*kt  ].w, ph[1], pl[1]);
            split2(acc[2*kt+1].x, acc[2*kt+1].y, ph[2], pl[2]);
            split2(acc[2*kt+1].z, acc[2*kt+1].w, ph[3], pl[3]);
            #pragma unroll
            for (int ntp = 0; ntp < 2; ntp++) {
                unsigned off = ((ntp*16 + bRow) * 36 + kt*8 + bSel) * 4u;
                unsigned th[4], tl[4];
                ldsm4(th, VhB + off);
                ldsm4(tl, VlB + off);
                mma3(O[2*ntp  ], ph, pl, th[0], th[1], tl[0], tl[1]);
                mma3(O[2*ntp+1], ph, pl, th[2], th[3], tl[2], tl[3]);
            }
        }
        __syncthreads();
    }

    // epilogue
    float inv0 = 1.f / l0, inv1 = 1.f / l1;
    float* ob = g_o + (size_t)(bh >> 3) * NTOK * DD + h * DH;
    #pragma unroll
    for (int nt = 0; nt < 4; nt++) {
        int e = nt*8 + 2*c;
        int p = q0 + wid*16 + r;
        if (p < NTOK)
            *(float2*)&ob[(size_t)p * DD + e] =
                make_float2(O[nt].x * inv0, O[nt].y * inv0);
        if (p + 8 < NTOK)
            *(float2*)&ob[(size_t)(p + 8) * DD + e] =
                make_float2(O[nt].z * inv1, O[nt].w * inv1);
    }
}

// ============================================================
// Kernel 3: output projection, bf16 3-mma + LDSM + transposed store.
// ============================================================
#define OUT_CS_WORDS (128*69)   // 8832 > AB words (2*128*20 + 2*64*20 = 7680)
#define OUT_SM_WORDS OUT_CS_WORDS

__global__ __launch_bounds__(256) void out_mma(const float* __restrict__ w,
                                               float* __restrict__ out) {
    __shared__ __align__(16) unsigned smbuf[OUT_SM_WORDS];
    unsigned (*Ah)[20] = (unsigned(*)[20])smbuf;
    unsigned (*Al)[20] = (unsigned(*)[20])(smbuf + 128*20);
    unsigned (*Bh)[20] = (unsigned(*)[20])(smbuf + 2*128*20);
    unsigned (*Bl)[20] = (unsigned(*)[20])(smbuf + 2*128*20 + 64*20);
    float    (*Cs)[69] = (float(*)[69])smbuf;

    int b  = blockIdx.z;
    int p0 = blockIdx.x * 128;
    int n0 = blockIdx.y * 64;
    int tid = threadIdx.x;
    int wid = tid >> 5, lane = tid & 31;
    int wm = wid & 3, wn = wid >> 2;
    int r = lane >> 2, c = lane & 3;

    float4 acc[2][4];
    #pragma unroll
    for (int i = 0; i < 2; i++)
        #pragma unroll
        for (int j = 0; j < 4; j++) acc[i][j] = make_float4(0,0,0,0);

    int am   = tid >> 1;
    int ahlf = tid & 1;
    int bn   = tid & 63;
    int bq   = tid >> 6;
    bool ap_ok = (p0 + am) < NTOK;

    int aRow = lane & 15;
    int aSel = (lane >> 4) * 4;
    int bRow = ((lane >> 4) << 3) | (lane & 7);
    int bSel = ((lane >> 3) & 1) * 4;
    unsigned AhB = sptr(Ah), AlB = sptr(Al), BhB = sptr(Bh), BlB = sptr(Bl);

    for (int k0 = 0; k0 < DD; k0 += 32) {
        {
            float av[16];
            if (ap_ok) {
                const float* src = &g_o[((size_t)b * NTOK + p0 + am) * DD + k0 + 16*ahlf];
                *(float4*)&av[0]  = *(const float4*)&src[0];
                *(float4*)&av[4]  = *(const float4*)&src[4];
                *(float4*)&av[8]  = *(const float4*)&src[8];
                *(float4*)&av[12] = *(const float4*)&src[12];
            } else {
                #pragma unroll
                for (int i = 0; i < 16; i++) av[i] = 0.f;
            }
            #pragma unroll
            for (int i = 0; i < 8; i++)
                split2(av[2*i], av[2*i+1],
                       Ah[am][8*ahlf + i], Al[am][8*ahlf + i]);
        }
        #pragma unroll
        for (int wd = 0; wd < 4; wd++) {
            int k = k0 + 8 * bq + 2 * wd;
            float f0 = w[(size_t)k * DD + n0 + bn];
            float f1 = w[(size_t)(k + 1) * DD + n0 + bn];
            split2(f0, f1, Bh[bn][4*bq + wd], Bl[bn][4*bq + wd]);
        }
        __syncthreads();

        #pragma unroll
        for (int ktl = 0; ktl < 2; ktl++) {
            unsigned ah[2][4], al[2][4];
            #pragma unroll
            for (int mt = 0; mt < 2; mt++) {
                unsigned off = ((wm*32 + mt*16 + aRow) * 20 + ktl*8 + aSel) * 4u;
                ldsm4(ah[mt], AhB + off);
                ldsm4(al[mt], AlB + off);
            }
            unsigned bhf[4][2], blf[4][2];
            #pragma unroll
            for (int ntp = 0; ntp < 2; ntp++) {
                unsigned off = ((wn*32 + ntp*16 + bRow) * 20 + ktl*8 + bSel) * 4u;
                unsigned t[4];
                ldsm4(t, BhB + off);
                bhf[2*ntp][0] = t[0]; bhf[2*ntp][1] = t[1];
                bhf[2*ntp+1][0] = t[2]; bhf[2*ntp+1][1] = t[3];
                ldsm4(t, BlB + off);
                blf[2*ntp][0] = t[0]; blf[2*ntp][1] = t[1];
                blf[2*ntp+1][0] = t[2]; blf[2*ntp+1][1] = t[3];
            }
            #pragma unroll
            for (int nt = 0; nt < 4; nt++)
                #pragma unroll
                for (int mt = 0; mt < 2; mt++)
                    mma3(acc[mt][nt], ah[mt], al[mt],
                         bhf[nt][0], bhf[nt][1], blf[nt][0], blf[nt][1]);
        }
        __syncthreads();
    }

    // C -> smem (unioned) -> coalesced transposed store
    #pragma unroll
    for (int mt = 0; mt < 2; mt++) {
        int m = wm * 32 + mt * 16 + r;
        #pragma unroll
        for (int nt = 0; nt < 4; nt++) {
            int n = wn * 32 + nt * 8 + 2 * c;
            Cs[m    ][n    ] = acc[mt][nt].x;
            Cs[m    ][n + 1] = acc[mt][nt].y;
            Cs[m + 8][n    ] = acc[mt][nt].z;
            Cs[m + 8][n + 1] = acc[mt][nt].w;
        }
    }
    __syncthreads();

    #pragma unroll
    for (int it = 0; it < 32; it++) {
        int idx = it * 256 + tid;
        int n = idx >> 7;
        int m = idx & 127;
        int p = p0 + m;
        if (p < NTOK)
            out[((size_t)b * DD + n0 + n) * NTOK + p] = Cs[m][n];
    }
}

// ============================================================
extern "C" void kernel_launch(void* const* d_in, const int* in_sizes, int n_in,
                              void* d_out, int out_size) {
    const float* x          = (const float*)d_in[0];
    const float* w_qkv      = (const float*)d_in[1];
    const float* w_out      = (const float*)d_in[2];
    const float* bias_table = (const float*)d_in[3];
    const int*   rel        = (const int*)d_in[4];
    float* out = (float*)d_out;

    bias_fill<<<(HEADS * NTOK * NTOK + 255) / 256, 256>>>(bias_table, rel);
    qkv_mma<<<dim3(5, 12, BB), 256>>>(x, w_qkv);
    attn_mma<<<dim3(5, BB * HEADS), 256>>>();
    out_mma<<<dim3(5, 4, BB), 256>>>(w_out, out);
}